// round 11
// baseline (speedup 1.0000x reference)
#include <cuda_runtime.h>

#define BATCH   8192
#define ROW_LEN 128
#define DIM     128
#define NBUCKET 64

// Deterministic partial reduction: fixed-point (2^38) integer buckets.
// Integer atomic adds are order-independent -> bit-exact across replays.
// 256B stride keeps buckets on distinct L2 slices (hash bit-7 pair-collision).
struct __align__(256) Bucket { unsigned long long v; };
__device__ Bucket g_buckets[NBUCKET];   // zero-initialized at module load

__global__ __launch_bounds__(128, 12)
void node2vec_row_kernel(const void* __restrict__ rt_raw,
                         const float* __restrict__ X,
                         const int* __restrict__ m_ptr) {
    const int b    = blockIdx.x;
    const int tid  = threadIdx.x;   // 0..127
    const int lane = tid & 31;
    const int warp = tid >> 5;      // 0..3

    __shared__ int   idx_s[ROW_LEN];
    __shared__ float x0s[DIM];
    __shared__ float scores[ROW_LEN];

    const int* __restrict__ rt32 = (const int*)rt_raw;

    // Runtime dtype detection: int64 (<2^31 values) => odd 32-bit words zero.
    const bool is64 = (rt32[1] == 0) & (rt32[3] == 0) & (rt32[5] == 0) & (rt32[7] == 0);

    const long long base = (long long)b * ROW_LEN;

    // Preload this row's 128 indices into shared (one coalesced pass).
    idx_s[tid] = is64 ? rt32[2 * (base + tid)] : rt32[base + tid];

    // x0 = X[rt[b,0]]
    {
        const long long e0 = is64 ? (long long)rt32[2 * base] : (long long)rt32[base];
        x0s[tid] = __ldg(X + e0 * DIM + tid);
    }
    __syncthreads();

    // Mixed-width layout per row: elements 0..63 as float2 (LDG.64),
    // elements 64..95 and 96..127 as scalar LDG.32.
    const float2* __restrict__ x02 = reinterpret_cast<const float2*>(x0s);
    const float2 x0p  = x02[lane];
    const float  x0c2 = x0s[64 + lane];
    const float  x0c3 = x0s[96 + lane];

    // 32-bit byte-offset addressing: max offset 100000*512 = 51.2MB < 2^31.
    const char* __restrict__ Xb = (const char*)X;
    const unsigned lane8  = (unsigned)lane * 8u;
    const unsigned lane4a = 256u + (unsigned)lane * 4u;
    const unsigned lane4b = 384u + (unsigned)lane * 4u;

    const int row0 = warp * 32;
    #pragma unroll
    for (int it = 0; it < 8; ++it) {
        const int l = row0 + it * 4;
        const unsigned o0 = (unsigned)idx_s[l + 0] * 512u;
        const unsigned o1 = (unsigned)idx_s[l + 1] * 512u;
        const unsigned o2 = (unsigned)idx_s[l + 2] * 512u;
        const unsigned o3 = (unsigned)idx_s[l + 3] * 512u;

        const float2 a01 = __ldg((const float2*)(Xb + o0 + lane8));
        const float2 b01 = __ldg((const float2*)(Xb + o1 + lane8));
        const float2 c01 = __ldg((const float2*)(Xb + o2 + lane8));
        const float2 e01 = __ldg((const float2*)(Xb + o3 + lane8));
        const float  a2 = __ldg((const float*)(Xb + o0 + lane4a));
        const float  a3 = __ldg((const float*)(Xb + o0 + lane4b));
        const float  b2 = __ldg((const float*)(Xb + o1 + lane4a));
        const float  b3 = __ldg((const float*)(Xb + o1 + lane4b));
        const float  c2 = __ldg((const float*)(Xb + o2 + lane4a));
        const float  c3 = __ldg((const float*)(Xb + o2 + lane4b));
        const float  e2 = __ldg((const float*)(Xb + o3 + lane4a));
        const float  e3 = __ldg((const float*)(Xb + o3 + lane4b));

        float d0 = a01.x * x0p.x + a01.y * x0p.y + a2 * x0c2 + a3 * x0c3;
        float d1 = b01.x * x0p.x + b01.y * x0p.y + b2 * x0c2 + b3 * x0c3;
        float d2 = c01.x * x0p.x + c01.y * x0p.y + c2 * x0c2 + c3 * x0c3;
        float d3 = e01.x * x0p.x + e01.y * x0p.y + e2 * x0c2 + e3 * x0c3;

        // Multi-row butterfly: 5 shfls reduce all 4 accumulators.
        float loA = (lane & 16) ? d1 : d0;
        float hiA = (lane & 16) ? d0 : d1;
        loA += __shfl_xor_sync(0xffffffffu, hiA, 16);
        float loB = (lane & 16) ? d3 : d2;
        float hiB = (lane & 16) ? d2 : d3;
        loB += __shfl_xor_sync(0xffffffffu, hiB, 16);
        float lo = (lane & 8) ? loB : loA;
        float hi = (lane & 8) ? loA : loB;
        lo += __shfl_xor_sync(0xffffffffu, hi, 8);
        #pragma unroll
        for (int off = 4; off > 0; off >>= 1)
            lo += __shfl_xor_sync(0xffffffffu, lo, off);

        if ((lane & 7) == 0) {
            const int g = lane >> 3;
            const int sel = (g & 1) * 2 + (g >> 1); // {0,2,1,3}
            scores[l + sel] = lo;
        }
    }
    __syncthreads();

    // Warp 0: softmax stats, then one fire-and-forget integer RED per CTA.
    if (warp == 0) {
        const int m = m_ptr[0];
        const float s0 = scores[lane];
        const float s1 = scores[lane + 32];
        const float s2 = scores[lane + 64];
        const float s3 = scores[lane + 96];

        float mx = fmaxf(fmaxf(s0, s1), fmaxf(s2, s3));
        #pragma unroll
        for (int off = 16; off > 0; off >>= 1)
            mx = fmaxf(mx, __shfl_xor_sync(0xffffffffu, mx, off));

        float e = __expf(s0 - mx) + __expf(s1 - mx) + __expf(s2 - mx) + __expf(s3 - mx);
        float p = 0.0f;
        if (lane >= 1 && lane <= m)        p += s0;
        if (lane + 32 <= m)                p += s1;
        if (lane + 64 <= m)                p += s2;
        if (lane + 96 <= m)                p += s3;
        #pragma unroll
        for (int off = 16; off > 0; off >>= 1) {
            e += __shfl_xor_sync(0xffffffffu, e, off);
            p += __shfl_xor_sync(0xffffffffu, p, off);
        }

        if (lane == 0) {
            const float lse  = mx + __logf(e);
            const float loss = (float)m * lse - p;
            // Fixed-point 2^38 quantization -> exact, order-independent sum.
            const double SCALE = 274877906944.0;    // 2^38
            const long long q = llrint((double)loss * SCALE);
            atomicAdd(&g_buckets[b & (NBUCKET - 1)].v, (unsigned long long)q);
            // No fence: the subsequent kernel launch orders visibility.
        }
    }
}

__global__ __launch_bounds__(32)
void node2vec_reduce_kernel(float* __restrict__ out) {
    const int lane = threadIdx.x;   // single warp
    // 64 buckets, 2 per lane; one dependent L2 round.
    long long q = (long long)g_buckets[lane].v
                + (long long)g_buckets[lane + 32].v;
    // Reset for next graph replay (each lane resets what it read).
    g_buckets[lane].v      = 0ULL;
    g_buckets[lane + 32].v = 0ULL;
    #pragma unroll
    for (int off = 16; off > 0; off >>= 1)
        q += __shfl_xor_sync(0xffffffffu, q, off);
    if (lane == 0) {
        const double SCALE = 274877906944.0;        // 2^38
        out[0] = (float)((double)q / SCALE / (double)BATCH);
    }
}

extern "C" void kernel_launch(void* const* d_in, const int* in_sizes, int n_in,
                              void* d_out, int out_size) {
    const void*  rt = d_in[0];                 // rt_batch [8192,128] int32 or int64
    const float* X  = (const float*)d_in[1];   // X float32 [100000,128]
    const int*   m  = (const int*)d_in[2];     // m scalar
    float* out = (float*)d_out;

    node2vec_row_kernel<<<BATCH, 128>>>(rt, X, m);
    node2vec_reduce_kernel<<<1, 32>>>(out);
}